// round 15
// baseline (speedup 1.0000x reference)
#include <cuda_runtime.h>
#include <cuda_fp16.h>
#include <math.h>

#define NN 1200000
#define EE 12000000
#define BB 200000

// ---------------- scratch (device globals: allocation-free) ----------------
__device__ __align__(16) float g_deg[NN];
__device__ __align__(16) float g_dinv[NN];
// layer-1 features: fp16, 16 halves per row = 32B = ONE L2 sector (38.4MB)
// lanes 10-15 zero. Atomic accumulators remain fp32.
__device__ __align__(32) __half g_xs1h[(size_t)NN * 16];
__device__ __align__(32) float g_agg1a[(size_t)NN * 8];  // raw sums 0-7 (38.4MB)
__device__ __align__(16) float g_agg1b[(size_t)NN * 2];  // raw sums 8-9 ( 9.6MB)
// layer-2: 8-float padded rows (one 32B sector per row; lanes 5-7 zero)
__device__ __align__(32) float g_ys2[(size_t)NN * 8];    // h2*dinv    (38.4MB)
__device__ __align__(32) float g_agg2[(size_t)NN * 8];   // raw sums   (38.4MB)

// sin(0..9): positional encoding (d_model=1 -> only sin slice)
__constant__ float PO[10] = {
    0.0f, 0.8414709848f, 0.9092974268f, 0.1411200081f, -0.7568024953f,
    -0.9589242747f, -0.2794154982f, 0.6569865987f, 0.9893582466f, 0.4121184852f
};

__device__ __forceinline__ float gelu_f(float x) {
    return 0.5f * x * (1.0f + erff(x * 0.7071067811865475f));
}

__device__ __forceinline__ void red4(float* p, float a, float b, float c, float d) {
    asm volatile("red.global.add.v4.f32 [%0], {%1,%2,%3,%4};"
                 :: "l"(p), "f"(a), "f"(b), "f"(c), "f"(d) : "memory");
}
__device__ __forceinline__ void red2(float* p, float a, float b) {
    asm volatile("red.global.add.v2.f32 [%0], {%1,%2};"
                 :: "l"(p), "f"(a), "f"(b) : "memory");
}
// streaming 256-bit load of 8 edge indices (evict_first keeps the 96MB index
// stream from evicting the L2-resident feature/accumulator arrays)
__device__ __forceinline__ void ldg_stream8(const int* p, int* v) {
    asm volatile("ld.global.nc.L2::evict_first.v8.b32 "
                 "{%0,%1,%2,%3,%4,%5,%6,%7}, [%8];"
                 : "=r"(v[0]), "=r"(v[1]), "=r"(v[2]), "=r"(v[3]),
                   "=r"(v[4]), "=r"(v[5]), "=r"(v[6]), "=r"(v[7])
                 : "l"(p));
}
// 128-bit read-only gather (first 5 half2 of a row live in 16B+4B; we load
// the full 32B row as two 16B ops only where needed)
__device__ __forceinline__ void ldg_row4u(const void* p, unsigned* v) {
    asm volatile("ld.global.nc.v4.b32 {%0,%1,%2,%3}, [%4];"
                 : "=r"(v[0]), "=r"(v[1]), "=r"(v[2]), "=r"(v[3])
                 : "l"(p));
}

// ---------------- kernels ----------------

__global__ void k_init_deg() {
    int n = blockIdx.x * blockDim.x + threadIdx.x;
    if (n < NN) g_deg[n] = 1.0f;   // self-loop
}

// 8 edges per thread
__global__ void k_deg(const int* __restrict__ ei) {
    int t = blockIdx.x * blockDim.x + threadIdx.x;
    int e0 = t * 8;
    if (e0 >= EE) return;
    int d[8];
    ldg_stream8(ei + EE + e0, d);
    #pragma unroll
    for (int i = 0; i < 8; i++) atomicAdd(&g_deg[d[i]], 1.0f);
}

// prep: dinv, xs1h = fp16((x+po)*dinv) padded to 16 halves,
//       agg1_raw = fp32 xs1 (self-loop term, FULL precision)
__global__ void k_prep(const float* __restrict__ x) {
    int n = blockIdx.x * blockDim.x + threadIdx.x;
    if (n >= NN) return;
    float di = rsqrtf(g_deg[n]);
    g_dinv[n] = di;

    const float2* xp = (const float2*)(x + (size_t)n * 10);
    float v[10];
    #pragma unroll
    for (int i = 0; i < 5; i++) {
        float2 t = xp[i];
        v[2 * i]     = (t.x + PO[2 * i]) * di;
        v[2 * i + 1] = (t.y + PO[2 * i + 1]) * di;
    }
    // fp16 row (16 halves = 32B), lanes 10-15 zero
    __half2* hp = (__half2*)(g_xs1h + (size_t)n * 16);
    #pragma unroll
    for (int i = 0; i < 5; i++)
        hp[i] = __float22half2_rn(make_float2(v[2 * i], v[2 * i + 1]));
    hp[5] = __half2half2(__float2half(0.0f));
    hp[6] = hp[5];
    hp[7] = hp[5];
    // fp32 self-loop init of accumulators
    float4* aa = (float4*)(g_agg1a + (size_t)n * 8);
    aa[0] = make_float4(v[0], v[1], v[2], v[3]);
    aa[1] = make_float4(v[4], v[5], v[6], v[7]);
    *(float2*)(g_agg1b + (size_t)n * 2) = make_float2(v[8], v[9]);
}

// edge scatter layer 1: agg1_raw[dst] += xs1[src], 8 edges/thread.
// Structure: ALL gathers first (MLP=8), then all conversions+reductions.
// Per edge: one 16B + one 4B gather (same 32B sector), red4+red4+red2 fp32.
__global__ void k_scatter1(const int* __restrict__ ei) {
    int t = blockIdx.x * blockDim.x + threadIdx.x;
    int e0 = t * 8;
    if (e0 >= EE) return;
    int s[8], d[8];
    ldg_stream8(ei + e0, s);
    ldg_stream8(ei + EE + e0, d);
    // batch-issue all row gathers (both parts hit the same 32B sector)
    unsigned u0[8][4];   // half2 lanes 0-3 (comps 0-7)
    unsigned u4[8];      // half2 lane 4   (comps 8-9)
    #pragma unroll
    for (int i = 0; i < 8; i++) {
        const __half* row = g_xs1h + (size_t)s[i] * 16;
        ldg_row4u(row, u0[i]);
        u4[i] = __ldg((const unsigned*)(row + 8));
    }
    #pragma unroll
    for (int i = 0; i < 8; i++) {
        float2 f0 = __half22float2(*(__half2*)&u0[i][0]);
        float2 f1 = __half22float2(*(__half2*)&u0[i][1]);
        float2 f2 = __half22float2(*(__half2*)&u0[i][2]);
        float2 f3 = __half22float2(*(__half2*)&u0[i][3]);
        float2 f4 = __half22float2(*(__half2*)&u4[i]);
        float* aa = g_agg1a + (size_t)d[i] * 8;
        red4(aa,     f0.x, f0.y, f1.x, f1.y);
        red4(aa + 4, f2.x, f2.y, f3.x, f3.y);
        red2(g_agg1b + (size_t)d[i] * 2, f4.x, f4.y);
    }
}

// mid: u = dinv*agg1_raw; x2 = gelu(u@W1 + b1); h2 = x2@W2;
//      ys2 = h2*dinv (pad 8, zeros in 5-7); agg2_raw = ys2 (self-loop term)
__global__ void k_mid(const float* __restrict__ W1, const float* __restrict__ b1,
                      const float* __restrict__ W2) {
    __shared__ float sW1[200], sW2[100], sb1[20];
    for (int i = threadIdx.x; i < 200; i += blockDim.x) sW1[i] = W1[i];
    for (int i = threadIdx.x; i < 100; i += blockDim.x) sW2[i] = W2[i];
    for (int i = threadIdx.x; i < 20;  i += blockDim.x) sb1[i] = b1[i];
    __syncthreads();
    int n = blockIdx.x * blockDim.x + threadIdx.x;
    if (n >= NN) return;

    float di = g_dinv[n];
    const float4* aa = (const float4*)(g_agg1a + (size_t)n * 8);
    float4 a0 = aa[0], a1 = aa[1];
    float2 a2 = *(const float2*)(g_agg1b + (size_t)n * 2);
    float u[10];
    u[0]=a0.x*di; u[1]=a0.y*di; u[2]=a0.z*di; u[3]=a0.w*di;
    u[4]=a1.x*di; u[5]=a1.y*di; u[6]=a1.z*di; u[7]=a1.w*di;
    u[8]=a2.x*di; u[9]=a2.y*di;

    float h1[20];
    #pragma unroll
    for (int j = 0; j < 20; j++) h1[j] = sb1[j];
    #pragma unroll
    for (int i = 0; i < 10; i++) {
        float xi = u[i];
        #pragma unroll
        for (int j = 0; j < 20; j++) h1[j] = fmaf(xi, sW1[i * 20 + j], h1[j]);
    }
    float h2[5] = {0.f, 0.f, 0.f, 0.f, 0.f};
    #pragma unroll
    for (int i = 0; i < 20; i++) {
        float xi = gelu_f(h1[i]);
        #pragma unroll
        for (int j = 0; j < 5; j++) h2[j] = fmaf(xi, sW2[i * 5 + j], h2[j]);
    }
    float4* yp = (float4*)(g_ys2 + (size_t)n * 8);
    float4* gp = (float4*)(g_agg2 + (size_t)n * 8);
    float4 v0 = make_float4(h2[0]*di, h2[1]*di, h2[2]*di, h2[3]*di);
    float4 v1 = make_float4(h2[4]*di, 0.f, 0.f, 0.f);
    yp[0] = v0; yp[1] = v1;
    gp[0] = v0; gp[1] = v1;
}

// edge scatter layer 2: agg2_raw[dst] += ys2[src], 8 edges/thread.
// R12 structure: batch all gathers (MLP=8), then reductions.
__global__ void k_scatter2(const int* __restrict__ ei) {
    int t = blockIdx.x * blockDim.x + threadIdx.x;
    int e0 = t * 8;
    if (e0 >= EE) return;
    int s[8], d[8];
    ldg_stream8(ei + e0, s);
    ldg_stream8(ei + EE + e0, d);
    float4 v0[8];
    float  v4[8];
    #pragma unroll
    for (int i = 0; i < 8; i++) {
        const float4* sp = (const float4*)(g_ys2 + (size_t)s[i] * 8);
        v0[i] = __ldg(sp);
        v4[i] = __ldg((const float*)(sp + 1));
    }
    #pragma unroll
    for (int i = 0; i < 8; i++) {
        float* ap = g_agg2 + (size_t)d[i] * 8;
        red4(ap, v0[i].x, v0[i].y, v0[i].z, v0[i].w);
        atomicAdd(ap + 4, v4[i]);
    }
}

// heads: r = gelu(dinv*agg2_raw + b2) reshaped [B,30]; enc=r@We+be;
// x1=enc@Wr+br; out=gelu(enc)@Wd+bd.  d_out = [x1 | enc | out]
__global__ void k_head(const float* __restrict__ b2,
                       const float* __restrict__ We, const float* __restrict__ be,
                       const float* __restrict__ Wd, const float* __restrict__ bd,
                       const float* __restrict__ Wr, const float* __restrict__ br,
                       float* __restrict__ out) {
    __shared__ float sWe[900], sWd[1800], sWr[210];
    __shared__ float sbe[30], sbd[60], sbr[7], sb2[5];
    for (int i = threadIdx.x; i < 900; i += blockDim.x) sWe[i] = We[i];
    for (int i = threadIdx.x; i < 1800; i += blockDim.x) sWd[i] = Wd[i];
    for (int i = threadIdx.x; i < 210; i += blockDim.x) sWr[i] = Wr[i];
    if (threadIdx.x < 30) sbe[threadIdx.x] = be[threadIdx.x];
    if (threadIdx.x < 60) sbd[threadIdx.x] = bd[threadIdx.x];
    if (threadIdx.x < 7)  sbr[threadIdx.x] = br[threadIdx.x];
    if (threadIdx.x < 5)  sb2[threadIdx.x] = b2[threadIdx.x];
    __syncthreads();
    int b = blockIdx.x * blockDim.x + threadIdx.x;
    if (b >= BB) return;

    float r[30];
    #pragma unroll
    for (int v = 0; v < 6; v++) {
        int n = b * 6 + v;
        float di = g_dinv[n];
        const float* ag = g_agg2 + (size_t)n * 8;
        #pragma unroll
        for (int c = 0; c < 5; c++) r[v * 5 + c] = gelu_f(ag[c] * di + sb2[c]);
    }
    float enc[30];
    #pragma unroll 1
    for (int j = 0; j < 30; j++) {
        float a = sbe[j];
        #pragma unroll
        for (int k = 0; k < 30; k++) a = fmaf(r[k], sWe[k * 30 + j], a);
        enc[j] = a;
    }
    float* x1o  = out;
    float* enco = out + (size_t)BB * 7;
    float* oo   = out + (size_t)BB * 37;
    #pragma unroll 1
    for (int j = 0; j < 7; j++) {
        float a = sbr[j];
        #pragma unroll
        for (int k = 0; k < 30; k++) a = fmaf(enc[k], sWr[k * 7 + j], a);
        x1o[(size_t)b * 7 + j] = a;
    }
    float ge[30];
    #pragma unroll
    for (int k = 0; k < 30; k++) {
        enco[(size_t)b * 30 + k] = enc[k];
        ge[k] = gelu_f(enc[k]);
    }
    #pragma unroll 1
    for (int j = 0; j < 60; j++) {
        float a = sbd[j];
        #pragma unroll
        for (int k = 0; k < 30; k++) a = fmaf(ge[k], sWd[k * 60 + j], a);
        oo[(size_t)b * 60 + j] = a;
    }
}

// ---------------- launch ----------------
extern "C" void kernel_launch(void* const* d_in, const int* in_sizes, int n_in,
                              void* d_out, int out_size) {
    const float* x  = (const float*)d_in[0];
    const int*   ei = (const int*)  d_in[1];
    const float* W1 = (const float*)d_in[2];
    const float* b1 = (const float*)d_in[3];
    const float* W2 = (const float*)d_in[4];
    const float* b2 = (const float*)d_in[5];
    const float* We = (const float*)d_in[6];
    const float* be = (const float*)d_in[7];
    const float* Wd = (const float*)d_in[8];
    const float* bd = (const float*)d_in[9];
    const float* Wr = (const float*)d_in[10];
    const float* br = (const float*)d_in[11];
    float* out = (float*)d_out;

    const int TB = 256;
    const int E8 = EE / 8;  // 12M divisible by 8
    k_init_deg<<<(NN + TB - 1) / TB, TB>>>();
    k_deg<<<(E8 + TB - 1) / TB, TB>>>(ei);
    k_prep<<<(NN + TB - 1) / TB, TB>>>(x);
    k_scatter1<<<(E8 + TB - 1) / TB, TB>>>(ei);
    k_mid<<<(NN + TB - 1) / TB, TB>>>(W1, b1, W2);
    k_scatter2<<<(E8 + TB - 1) / TB, TB>>>(ei);
    k_head<<<(BB + 127) / 128, 128>>>(b2, We, be, Wd, bd, Wr, br, out);
}

// round 16
// speedup vs baseline: 1.4541x; 1.4541x over previous
#include <cuda_runtime.h>
#include <math.h>

#define NN 1200000
#define EE 12000000
#define BB 200000

// ---------------- scratch (device globals: allocation-free) ----------------
__device__ __align__(16) float g_deg[NN];
__device__ __align__(16) float g_dinv[NN];
// layer-1 features split: 8-float rows (32B sector-aligned) + 2-float rows
__device__ __align__(32) float g_xs1a[(size_t)NN * 8];   // comps 0-7  (38.4MB)
__device__ __align__(16) float g_xs1b[(size_t)NN * 2];   // comps 8-9  ( 9.6MB)
__device__ __align__(32) float g_agg1a[(size_t)NN * 8];  // raw sums   (38.4MB)
__device__ __align__(16) float g_agg1b[(size_t)NN * 2];  //            ( 9.6MB)
// layer-2: 8-float padded rows (one 32B sector per row; lanes 5-7 zero)
__device__ __align__(32) float g_ys2[(size_t)NN * 8];    // h2*dinv    (38.4MB)
__device__ __align__(32) float g_agg2[(size_t)NN * 8];   // raw sums   (38.4MB)

// sin(0..9): positional encoding (d_model=1 -> only sin slice)
__constant__ float PO[10] = {
    0.0f, 0.8414709848f, 0.9092974268f, 0.1411200081f, -0.7568024953f,
    -0.9589242747f, -0.2794154982f, 0.6569865987f, 0.9893582466f, 0.4121184852f
};

__device__ __forceinline__ float gelu_f(float x) {
    return 0.5f * x * (1.0f + erff(x * 0.7071067811865475f));
}

__device__ __forceinline__ void red4(float* p, float a, float b, float c, float d) {
    asm volatile("red.global.add.v4.f32 [%0], {%1,%2,%3,%4};"
                 :: "l"(p), "f"(a), "f"(b), "f"(c), "f"(d) : "memory");
}
__device__ __forceinline__ void red2(float* p, float a, float b) {
    asm volatile("red.global.add.v2.f32 [%0], {%1,%2};"
                 :: "l"(p), "f"(a), "f"(b) : "memory");
}
// streaming 256-bit load of 8 edge indices (evict_first keeps the 96MB index
// stream from evicting the L2-resident feature/accumulator arrays)
__device__ __forceinline__ void ldg_stream8(const int* p, int* v) {
    asm volatile("ld.global.nc.L2::evict_first.v8.b32 "
                 "{%0,%1,%2,%3,%4,%5,%6,%7}, [%8];"
                 : "=r"(v[0]), "=r"(v[1]), "=r"(v[2]), "=r"(v[3]),
                   "=r"(v[4]), "=r"(v[5]), "=r"(v[6]), "=r"(v[7])
                 : "l"(p));
}
// 256-bit read-only gather of one 8-float (32B) row in a single instruction
__device__ __forceinline__ void ldg_row8f(const float* p, float* v) {
    asm volatile("ld.global.nc.v8.b32 {%0,%1,%2,%3,%4,%5,%6,%7}, [%8];"
                 : "=f"(v[0]), "=f"(v[1]), "=f"(v[2]), "=f"(v[3]),
                   "=f"(v[4]), "=f"(v[5]), "=f"(v[6]), "=f"(v[7])
                 : "l"(p));
}

// ---------------- kernels ----------------

__global__ void k_init_deg() {
    int n = blockIdx.x * blockDim.x + threadIdx.x;
    if (n < NN) g_deg[n] = 1.0f;   // self-loop
}

// 8 edges per thread
__global__ void k_deg(const int* __restrict__ ei) {
    int t = blockIdx.x * blockDim.x + threadIdx.x;
    int e0 = t * 8;
    if (e0 >= EE) return;
    int d[8];
    ldg_stream8(ei + EE + e0, d);
    #pragma unroll
    for (int i = 0; i < 8; i++) atomicAdd(&g_deg[d[i]], 1.0f);
}

// prep: dinv, xs1 = (x+po)*dinv  (split 8+2), agg1_raw = xs1 (self-loop term)
__global__ void k_prep(const float* __restrict__ x) {
    int n = blockIdx.x * blockDim.x + threadIdx.x;
    if (n >= NN) return;
    float di = rsqrtf(g_deg[n]);
    g_dinv[n] = di;

    const float2* xp = (const float2*)(x + (size_t)n * 10);
    float v[10];
    #pragma unroll
    for (int i = 0; i < 5; i++) {
        float2 t = xp[i];
        v[2 * i]     = (t.x + PO[2 * i]) * di;
        v[2 * i + 1] = (t.y + PO[2 * i + 1]) * di;
    }
    float4 w0 = make_float4(v[0], v[1], v[2], v[3]);
    float4 w1 = make_float4(v[4], v[5], v[6], v[7]);
    float2 w2 = make_float2(v[8], v[9]);
    float4* sa = (float4*)(g_xs1a + (size_t)n * 8);
    float4* aa = (float4*)(g_agg1a + (size_t)n * 8);
    sa[0] = w0; sa[1] = w1;
    aa[0] = w0; aa[1] = w1;
    *(float2*)(g_xs1b  + (size_t)n * 2) = w2;
    *(float2*)(g_agg1b + (size_t)n * 2) = w2;
}

// edge scatter layer 1: agg1_raw[dst] += xs1[src], 8 edges/thread.
// R12 structure (batch all gathers, then all reductions); the only change:
// the 8-float row gather is ONE 256-bit load instead of two float4 loads.
__global__ void k_scatter1(const int* __restrict__ ei) {
    int t = blockIdx.x * blockDim.x + threadIdx.x;
    int e0 = t * 8;
    if (e0 >= EE) return;
    int s[8], d[8];
    ldg_stream8(ei + e0, s);
    ldg_stream8(ei + EE + e0, d);
    // issue all gathers first (MLP), then the reductions
    float va[8][8];
    float2 vb[8];
    #pragma unroll
    for (int i = 0; i < 8; i++) {
        ldg_row8f(g_xs1a + (size_t)s[i] * 8, va[i]);
        vb[i] = __ldg((const float2*)(g_xs1b + (size_t)s[i] * 2));
    }
    #pragma unroll
    for (int i = 0; i < 8; i++) {
        float* aa = g_agg1a + (size_t)d[i] * 8;
        red4(aa,     va[i][0], va[i][1], va[i][2], va[i][3]);
        red4(aa + 4, va[i][4], va[i][5], va[i][6], va[i][7]);
        red2(g_agg1b + (size_t)d[i] * 2, vb[i].x, vb[i].y);
    }
}

// mid: u = dinv*agg1_raw; x2 = gelu(u@W1 + b1); h2 = x2@W2;
//      ys2 = h2*dinv (pad 8, zeros in 5-7); agg2_raw = ys2 (self-loop term)
__global__ void k_mid(const float* __restrict__ W1, const float* __restrict__ b1,
                      const float* __restrict__ W2) {
    __shared__ float sW1[200], sW2[100], sb1[20];
    for (int i = threadIdx.x; i < 200; i += blockDim.x) sW1[i] = W1[i];
    for (int i = threadIdx.x; i < 100; i += blockDim.x) sW2[i] = W2[i];
    for (int i = threadIdx.x; i < 20;  i += blockDim.x) sb1[i] = b1[i];
    __syncthreads();
    int n = blockIdx.x * blockDim.x + threadIdx.x;
    if (n >= NN) return;

    float di = g_dinv[n];
    const float4* aa = (const float4*)(g_agg1a + (size_t)n * 8);
    float4 a0 = aa[0], a1 = aa[1];
    float2 a2 = *(const float2*)(g_agg1b + (size_t)n * 2);
    float u[10];
    u[0]=a0.x*di; u[1]=a0.y*di; u[2]=a0.z*di; u[3]=a0.w*di;
    u[4]=a1.x*di; u[5]=a1.y*di; u[6]=a1.z*di; u[7]=a1.w*di;
    u[8]=a2.x*di; u[9]=a2.y*di;

    float h1[20];
    #pragma unroll
    for (int j = 0; j < 20; j++) h1[j] = sb1[j];
    #pragma unroll
    for (int i = 0; i < 10; i++) {
        float xi = u[i];
        #pragma unroll
        for (int j = 0; j < 20; j++) h1[j] = fmaf(xi, sW1[i * 20 + j], h1[j]);
    }
    float h2[5] = {0.f, 0.f, 0.f, 0.f, 0.f};
    #pragma unroll
    for (int i = 0; i < 20; i++) {
        float xi = gelu_f(h1[i]);
        #pragma unroll
        for (int j = 0; j < 5; j++) h2[j] = fmaf(xi, sW2[i * 5 + j], h2[j]);
    }
    float4* yp = (float4*)(g_ys2 + (size_t)n * 8);
    float4* gp = (float4*)(g_agg2 + (size_t)n * 8);
    float4 v0 = make_float4(h2[0]*di, h2[1]*di, h2[2]*di, h2[3]*di);
    float4 v1 = make_float4(h2[4]*di, 0.f, 0.f, 0.f);
    yp[0] = v0; yp[1] = v1;
    gp[0] = v0; gp[1] = v1;
}

// edge scatter layer 2: agg2_raw[dst] += ys2[src], 8 edges/thread.
// R12 structure; gather is ONE 256-bit load per edge.
__global__ void k_scatter2(const int* __restrict__ ei) {
    int t = blockIdx.x * blockDim.x + threadIdx.x;
    int e0 = t * 8;
    if (e0 >= EE) return;
    int s[8], d[8];
    ldg_stream8(ei + e0, s);
    ldg_stream8(ei + EE + e0, d);
    float v[8][8];
    #pragma unroll
    for (int i = 0; i < 8; i++) {
        ldg_row8f(g_ys2 + (size_t)s[i] * 8, v[i]);
    }
    #pragma unroll
    for (int i = 0; i < 8; i++) {
        float* ap = g_agg2 + (size_t)d[i] * 8;
        red4(ap, v[i][0], v[i][1], v[i][2], v[i][3]);
        atomicAdd(ap + 4, v[i][4]);
    }
}

// heads: r = gelu(dinv*agg2_raw + b2) reshaped [B,30]; enc=r@We+be;
// x1=enc@Wr+br; out=gelu(enc)@Wd+bd.  d_out = [x1 | enc | out]
__global__ void k_head(const float* __restrict__ b2,
                       const float* __restrict__ We, const float* __restrict__ be,
                       const float* __restrict__ Wd, const float* __restrict__ bd,
                       const float* __restrict__ Wr, const float* __restrict__ br,
                       float* __restrict__ out) {
    __shared__ float sWe[900], sWd[1800], sWr[210];
    __shared__ float sbe[30], sbd[60], sbr[7], sb2[5];
    for (int i = threadIdx.x; i < 900; i += blockDim.x) sWe[i] = We[i];
    for (int i = threadIdx.x; i < 1800; i += blockDim.x) sWd[i] = Wd[i];
    for (int i = threadIdx.x; i < 210; i += blockDim.x) sWr[i] = Wr[i];
    if (threadIdx.x < 30) sbe[threadIdx.x] = be[threadIdx.x];
    if (threadIdx.x < 60) sbd[threadIdx.x] = bd[threadIdx.x];
    if (threadIdx.x < 7)  sbr[threadIdx.x] = br[threadIdx.x];
    if (threadIdx.x < 5)  sb2[threadIdx.x] = b2[threadIdx.x];
    __syncthreads();
    int b = blockIdx.x * blockDim.x + threadIdx.x;
    if (b >= BB) return;

    float r[30];
    #pragma unroll
    for (int v = 0; v < 6; v++) {
        int n = b * 6 + v;
        float di = g_dinv[n];
        const float* ag = g_agg2 + (size_t)n * 8;
        #pragma unroll
        for (int c = 0; c < 5; c++) r[v * 5 + c] = gelu_f(ag[c] * di + sb2[c]);
    }
    float enc[30];
    #pragma unroll 1
    for (int j = 0; j < 30; j++) {
        float a = sbe[j];
        #pragma unroll
        for (int k = 0; k < 30; k++) a = fmaf(r[k], sWe[k * 30 + j], a);
        enc[j] = a;
    }
    float* x1o  = out;
    float* enco = out + (size_t)BB * 7;
    float* oo   = out + (size_t)BB * 37;
    #pragma unroll 1
    for (int j = 0; j < 7; j++) {
        float a = sbr[j];
        #pragma unroll
        for (int k = 0; k < 30; k++) a = fmaf(enc[k], sWr[k * 7 + j], a);
        x1o[(size_t)b * 7 + j] = a;
    }
    float ge[30];
    #pragma unroll
    for (int k = 0; k < 30; k++) {
        enco[(size_t)b * 30 + k] = enc[k];
        ge[k] = gelu_f(enc[k]);
    }
    #pragma unroll 1
    for (int j = 0; j < 60; j++) {
        float a = sbd[j];
        #pragma unroll
        for (int k = 0; k < 30; k++) a = fmaf(ge[k], sWd[k * 60 + j], a);
        oo[(size_t)b * 60 + j] = a;
    }
}

// ---------------- launch ----------------
extern "C" void kernel_launch(void* const* d_in, const int* in_sizes, int n_in,
                              void* d_out, int out_size) {
    const float* x  = (const float*)d_in[0];
    const int*   ei = (const int*)  d_in[1];
    const float* W1 = (const float*)d_in[2];
    const float* b1 = (const float*)d_in[3];
    const float* W2 = (const float*)d_in[4];
    const float* b2 = (const float*)d_in[5];
    const float* We = (const float*)d_in[6];
    const float* be = (const float*)d_in[7];
    const float* Wd = (const float*)d_in[8];
    const float* bd = (const float*)d_in[9];
    const float* Wr = (const float*)d_in[10];
    const float* br = (const float*)d_in[11];
    float* out = (float*)d_out;

    const int TB = 256;
    const int E8 = EE / 8;  // 12M divisible by 8
    k_init_deg<<<(NN + TB - 1) / TB, TB>>>();
    k_deg<<<(E8 + TB - 1) / TB, TB>>>(ei);
    k_prep<<<(NN + TB - 1) / TB, TB>>>(x);
    k_scatter1<<<(E8 + TB - 1) / TB, TB>>>(ei);
    k_mid<<<(NN + TB - 1) / TB, TB>>>(W1, b1, W2);
    k_scatter2<<<(E8 + TB - 1) / TB, TB>>>(ei);
    k_head<<<(BB + 127) / 128, 128>>>(b2, We, be, Wd, bd, Wr, br, out);
}